// round 15
// baseline (speedup 1.0000x reference)
#include <cuda_runtime.h>
#include <math.h>

#define BATCH 2
#define SEQ   2048
#define DMODEL 512
#define NHEAD 8
#define DK    64
#define NROWS (BATCH*SEQ)        // 4096
#define Y_ELEMS (NROWS*DMODEL)   // 2097152
#define BH (BATCH*NHEAD)         // 16

// 1/sqrt(512)
#define INV_TEMP 0.04419417382415922f
#define LN_EPS 1e-5f

// Scratch (static device allocs are allowed)
__device__ float g_Q[BH*SEQ*DK];   // [b*H+h][s][dk]
__device__ float g_K[BH*SEQ*DK];
__device__ float g_V[BH*SEQ*DK];
__device__ float g_O[NROWS*DMODEL];
__device__ float g_X[NROWS*DMODEL];

// ---------------------------------------------------------------------------
// Kernel 1: projection  dst[b,h,s,dk] = A[n,:] . W[o,:] + bias[o]
// A: [4096,512] row-major, W: [512,512] row-major (torch Linear => x @ W^T)
// BM=BN=64, BK=16, 256 threads, 4x4 micro-tile
// ---------------------------------------------------------------------------
__global__ __launch_bounds__(256) void proj_kernel(
    const float* __restrict__ A, const float* __restrict__ W,
    const float* __restrict__ bias, float* __restrict__ dst)
{
    __shared__ float As[16][64];
    __shared__ float Ws[16][64];
    const int t  = threadIdx.x;
    const int tx = t & 15, ty = t >> 4;
    const int row0 = blockIdx.x * 64;
    const int col0 = blockIdx.y * 64;
    const int lr = t & 63;     // row within tile
    const int lc = t >> 6;     // col group (4 floats)

    float acc[4][4] = {};

    for (int k0 = 0; k0 < DMODEL; k0 += 16) {
        float4 av = *(const float4*)&A[(size_t)(row0 + lr)*DMODEL + k0 + lc*4];
        float4 wv = *(const float4*)&W[(size_t)(col0 + lr)*DMODEL + k0 + lc*4];
        As[lc*4+0][lr] = av.x; As[lc*4+1][lr] = av.y;
        As[lc*4+2][lr] = av.z; As[lc*4+3][lr] = av.w;
        Ws[lc*4+0][lr] = wv.x; Ws[lc*4+1][lr] = wv.y;
        Ws[lc*4+2][lr] = wv.z; Ws[lc*4+3][lr] = wv.w;
        __syncthreads();
        #pragma unroll
        for (int k = 0; k < 16; k++) {
            float4 a = *(const float4*)&As[k][ty*4];
            float4 b = *(const float4*)&Ws[k][tx*4];
            acc[0][0] += a.x*b.x; acc[0][1] += a.x*b.y; acc[0][2] += a.x*b.z; acc[0][3] += a.x*b.w;
            acc[1][0] += a.y*b.x; acc[1][1] += a.y*b.y; acc[1][2] += a.y*b.z; acc[1][3] += a.y*b.w;
            acc[2][0] += a.z*b.x; acc[2][1] += a.z*b.y; acc[2][2] += a.z*b.z; acc[2][3] += a.z*b.w;
            acc[3][0] += a.w*b.x; acc[3][1] += a.w*b.y; acc[3][2] += a.w*b.z; acc[3][3] += a.w*b.w;
        }
        __syncthreads();
    }

    #pragma unroll
    for (int i = 0; i < 4; i++) {
        int n = row0 + ty*4 + i;
        int bb = n / SEQ, ss = n % SEQ;
        #pragma unroll
        for (int j = 0; j < 4; j++) {
            int o = col0 + tx*4 + j;
            int h = o >> 6, dk = o & 63;
            dst[(((size_t)(bb*NHEAD + h))*SEQ + ss)*DK + dk] = acc[i][j] + bias[o];
        }
    }
}

// ---------------------------------------------------------------------------
// Kernel 2: scores[q,k] = (Qh . Kh) * INV_TEMP for one (b,h); written to attn
// region of d_out laid out [h*B+b][q][k]. BM=BN=64, full K-dim (64) in smem.
// ---------------------------------------------------------------------------
__global__ __launch_bounds__(256) void scores_kernel(float* __restrict__ attn)
{
    __shared__ float Qs[64][64];   // [dk][q]
    __shared__ float Ks[64][64];   // [dk][k]
    const int t  = threadIdx.x;
    const int tx = t & 15, ty = t >> 4;
    const int q0 = blockIdx.x * 64;
    const int k0 = blockIdx.y * 64;
    const int bh = blockIdx.z;           // b*H + h
    const float* Qb = g_Q + (size_t)bh*SEQ*DK;
    const float* Kb = g_K + (size_t)bh*SEQ*DK;

    #pragma unroll
    for (int p = 0; p < 4; p++) {
        int flat = p*256 + t;
        int r  = flat & 63;
        int cg = flat >> 6;              // 0..15
        float4 qv = *(const float4*)&Qb[(size_t)(q0 + r)*DK + cg*4];
        float4 kv = *(const float4*)&Kb[(size_t)(k0 + r)*DK + cg*4];
        Qs[cg*4+0][r] = qv.x; Qs[cg*4+1][r] = qv.y; Qs[cg*4+2][r] = qv.z; Qs[cg*4+3][r] = qv.w;
        Ks[cg*4+0][r] = kv.x; Ks[cg*4+1][r] = kv.y; Ks[cg*4+2][r] = kv.z; Ks[cg*4+3][r] = kv.w;
    }
    __syncthreads();

    float acc[4][4] = {};
    #pragma unroll
    for (int k = 0; k < 64; k++) {
        float4 a = *(const float4*)&Qs[k][ty*4];
        float4 b = *(const float4*)&Ks[k][tx*4];
        acc[0][0] += a.x*b.x; acc[0][1] += a.x*b.y; acc[0][2] += a.x*b.z; acc[0][3] += a.x*b.w;
        acc[1][0] += a.y*b.x; acc[1][1] += a.y*b.y; acc[1][2] += a.y*b.z; acc[1][3] += a.y*b.w;
        acc[2][0] += a.z*b.x; acc[2][1] += a.z*b.y; acc[2][2] += a.z*b.z; acc[2][3] += a.z*b.w;
        acc[3][0] += a.w*b.x; acc[3][1] += a.w*b.y; acc[3][2] += a.w*b.z; acc[3][3] += a.w*b.w;
    }

    const int b = bh >> 3, h = bh & 7;
    float* obase = attn + ((size_t)(h*BATCH + b))*SEQ*SEQ;
    #pragma unroll
    for (int i = 0; i < 4; i++) {
        size_t rowoff = (size_t)(q0 + ty*4 + i) * SEQ;
        #pragma unroll
        for (int j = 0; j < 4; j++)
            obase[rowoff + k0 + tx*4 + j] = acc[i][j] * INV_TEMP;
    }
}

// ---------------------------------------------------------------------------
// Kernel 3: row softmax in place over rows of length 2048
// ---------------------------------------------------------------------------
__global__ __launch_bounds__(256) void softmax_kernel(float* __restrict__ attn)
{
    __shared__ float sbuf[8];
    float* p = attn + (size_t)blockIdx.x * SEQ;
    const int t = threadIdx.x;

    float4 v0 = ((const float4*)p)[t];
    float4 v1 = ((const float4*)p)[t + 256];

    float m = fmaxf(fmaxf(fmaxf(v0.x, v0.y), fmaxf(v0.z, v0.w)),
                    fmaxf(fmaxf(v1.x, v1.y), fmaxf(v1.z, v1.w)));
    #pragma unroll
    for (int o = 16; o > 0; o >>= 1) m = fmaxf(m, __shfl_xor_sync(0xffffffffu, m, o));
    if ((t & 31) == 0) sbuf[t >> 5] = m;
    __syncthreads();
    m = sbuf[0];
    #pragma unroll
    for (int w = 1; w < 8; w++) m = fmaxf(m, sbuf[w]);
    __syncthreads();

    v0.x = __expf(v0.x - m); v0.y = __expf(v0.y - m);
    v0.z = __expf(v0.z - m); v0.w = __expf(v0.w - m);
    v1.x = __expf(v1.x - m); v1.y = __expf(v1.y - m);
    v1.z = __expf(v1.z - m); v1.w = __expf(v1.w - m);

    float s = v0.x + v0.y + v0.z + v0.w + v1.x + v1.y + v1.z + v1.w;
    #pragma unroll
    for (int o = 16; o > 0; o >>= 1) s += __shfl_xor_sync(0xffffffffu, s, o);
    if ((t & 31) == 0) sbuf[t >> 5] = s;
    __syncthreads();
    s = sbuf[0];
    #pragma unroll
    for (int w = 1; w < 8; w++) s += sbuf[w];

    float inv = 1.0f / s;
    v0.x *= inv; v0.y *= inv; v0.z *= inv; v0.w *= inv;
    v1.x *= inv; v1.y *= inv; v1.z *= inv; v1.w *= inv;
    ((float4*)p)[t] = v0;
    ((float4*)p)[t + 256] = v1;
}

// ---------------------------------------------------------------------------
// Kernel 4: O[b, q, h*64+dk] = attn[h*B+b, q, :] . Vh[b,h, :, dk]
// BM=64 (q), BN=64 (dk), BK=32
// ---------------------------------------------------------------------------
__global__ __launch_bounds__(256) void pv_kernel(const float* __restrict__ attn)
{
    __shared__ float As[32][64];   // [k][q]
    __shared__ float Bs[32][64];   // [k][dk]
    const int t  = threadIdx.x;
    const int tx = t & 15, ty = t >> 4;
    const int q0 = blockIdx.x * 64;
    const int bh = blockIdx.z;
    const int b = bh >> 3, h = bh & 7;
    const float* Ab = attn + ((size_t)(h*BATCH + b))*SEQ*SEQ;
    const float* Vb = g_V + (size_t)bh*SEQ*DK;

    float acc[4][4] = {};

    for (int kk = 0; kk < SEQ; kk += 32) {
        #pragma unroll
        for (int p = 0; p < 2; p++) {
            int flat = p*256 + t;
            int r  = flat & 63;          // q row
            int cg = flat >> 6;          // 0..7
            float4 av = *(const float4*)&Ab[(size_t)(q0 + r)*SEQ + kk + cg*4];
            As[cg*4+0][r] = av.x; As[cg*4+1][r] = av.y;
            As[cg*4+2][r] = av.z; As[cg*4+3][r] = av.w;
        }
        #pragma unroll
        for (int p = 0; p < 2; p++) {
            int flat = p*256 + t;
            int r = flat >> 4;           // 0..31 k row
            int c = flat & 15;
            *(float4*)&Bs[r][c*4] = *(const float4*)&Vb[(size_t)(kk + r)*DK + c*4];
        }
        __syncthreads();
        #pragma unroll
        for (int k = 0; k < 32; k++) {
            float4 a = *(const float4*)&As[k][ty*4];
            float4 b4 = *(const float4*)&Bs[k][tx*4];
            acc[0][0] += a.x*b4.x; acc[0][1] += a.x*b4.y; acc[0][2] += a.x*b4.z; acc[0][3] += a.x*b4.w;
            acc[1][0] += a.y*b4.x; acc[1][1] += a.y*b4.y; acc[1][2] += a.y*b4.z; acc[1][3] += a.y*b4.w;
            acc[2][0] += a.z*b4.x; acc[2][1] += a.z*b4.y; acc[2][2] += a.z*b4.z; acc[2][3] += a.z*b4.w;
            acc[3][0] += a.w*b4.x; acc[3][1] += a.w*b4.y; acc[3][2] += a.w*b4.z; acc[3][3] += a.w*b4.w;
        }
        __syncthreads();
    }

    #pragma unroll
    for (int i = 0; i < 4; i++) {
        size_t n = (size_t)(b*SEQ + q0 + ty*4 + i);
        #pragma unroll
        for (int j = 0; j < 4; j++)
            g_O[n*DMODEL + h*DK + tx*4 + j] = acc[i][j];
    }
}

// ---------------------------------------------------------------------------
// Kernel 5: X[n,o] = O[n,:] . Wfc[o,:] + bfc[o] + resid[n,o]
// ---------------------------------------------------------------------------
__global__ __launch_bounds__(256) void fc_kernel(
    const float* __restrict__ W, const float* __restrict__ bias,
    const float* __restrict__ resid)
{
    __shared__ float As[16][64];
    __shared__ float Ws[16][64];
    const int t  = threadIdx.x;
    const int tx = t & 15, ty = t >> 4;
    const int row0 = blockIdx.x * 64;
    const int col0 = blockIdx.y * 64;
    const int lr = t & 63;
    const int lc = t >> 6;

    float acc[4][4] = {};

    for (int k0 = 0; k0 < DMODEL; k0 += 16) {
        float4 av = *(const float4*)&g_O[(size_t)(row0 + lr)*DMODEL + k0 + lc*4];
        float4 wv = *(const float4*)&W[(size_t)(col0 + lr)*DMODEL + k0 + lc*4];
        As[lc*4+0][lr] = av.x; As[lc*4+1][lr] = av.y;
        As[lc*4+2][lr] = av.z; As[lc*4+3][lr] = av.w;
        Ws[lc*4+0][lr] = wv.x; Ws[lc*4+1][lr] = wv.y;
        Ws[lc*4+2][lr] = wv.z; Ws[lc*4+3][lr] = wv.w;
        __syncthreads();
        #pragma unroll
        for (int k = 0; k < 16; k++) {
            float4 a = *(const float4*)&As[k][ty*4];
            float4 b = *(const float4*)&Ws[k][tx*4];
            acc[0][0] += a.x*b.x; acc[0][1] += a.x*b.y; acc[0][2] += a.x*b.z; acc[0][3] += a.x*b.w;
            acc[1][0] += a.y*b.x; acc[1][1] += a.y*b.y; acc[1][2] += a.y*b.z; acc[1][3] += a.y*b.w;
            acc[2][0] += a.z*b.x; acc[2][1] += a.z*b.y; acc[2][2] += a.z*b.z; acc[2][3] += a.z*b.w;
            acc[3][0] += a.w*b.x; acc[3][1] += a.w*b.y; acc[3][2] += a.w*b.z; acc[3][3] += a.w*b.w;
        }
        __syncthreads();
    }

    #pragma unroll
    for (int i = 0; i < 4; i++) {
        size_t n = (size_t)(row0 + ty*4 + i);
        #pragma unroll
        for (int j = 0; j < 4; j++) {
            int o = col0 + tx*4 + j;
            g_X[n*DMODEL + o] = acc[i][j] + bias[o] + resid[n*DMODEL + o];
        }
    }
}

// ---------------------------------------------------------------------------
// Kernel 6: LayerNorm over rows of 512 -> y region of d_out
// ---------------------------------------------------------------------------
__global__ __launch_bounds__(256) void ln_kernel(
    const float* __restrict__ gamma, const float* __restrict__ beta,
    float* __restrict__ Y)
{
    __shared__ float sbuf[16];
    const size_t row = blockIdx.x;
    const int t = threadIdx.x;
    const float* x = g_X + row*DMODEL;

    float2 v = ((const float2*)x)[t];
    float s  = v.x + v.y;
    float ss = v.x*v.x + v.y*v.y;
    #pragma unroll
    for (int o = 16; o > 0; o >>= 1) {
        s  += __shfl_xor_sync(0xffffffffu, s, o);
        ss += __shfl_xor_sync(0xffffffffu, ss, o);
    }
    if ((t & 31) == 0) { sbuf[t >> 5] = s; sbuf[8 + (t >> 5)] = ss; }
    __syncthreads();
    s = 0.f; ss = 0.f;
    #pragma unroll
    for (int w = 0; w < 8; w++) { s += sbuf[w]; ss += sbuf[8 + w]; }

    float mu  = s * (1.0f / DMODEL);
    float var = ss * (1.0f / DMODEL) - mu * mu;
    float inv = rsqrtf(var + LN_EPS);

    float2 g = ((const float2*)gamma)[t];
    float2 bt = ((const float2*)beta)[t];
    float2 y;
    y.x = (v.x - mu) * inv * g.x + bt.x;
    y.y = (v.y - mu) * inv * g.y + bt.y;
    ((float2*)(Y + row*DMODEL))[t] = y;
}

// ---------------------------------------------------------------------------
extern "C" void kernel_launch(void* const* d_in, const int* in_sizes, int n_in,
                              void* d_out, int out_size)
{
    const float* q     = (const float*)d_in[0];
    const float* k     = (const float*)d_in[1];
    const float* v     = (const float*)d_in[2];
    const float* Wq    = (const float*)d_in[3];
    const float* bq    = (const float*)d_in[4];
    const float* Wk    = (const float*)d_in[5];
    const float* bk    = (const float*)d_in[6];
    const float* Wv    = (const float*)d_in[7];
    const float* bv    = (const float*)d_in[8];
    const float* Wfc   = (const float*)d_in[9];
    const float* bfc   = (const float*)d_in[10];
    const float* gamma = (const float*)d_in[11];
    const float* beta  = (const float*)d_in[12];

    float* out  = (float*)d_out;
    float* attn = out + Y_ELEMS;

    float* dQ; cudaGetSymbolAddress((void**)&dQ, g_Q);
    float* dK; cudaGetSymbolAddress((void**)&dK, g_K);
    float* dV; cudaGetSymbolAddress((void**)&dV, g_V);

    dim3 blk(256);

    // 1) QKV projections into head-split layout
    dim3 gproj(NROWS/64, DMODEL/64);
    proj_kernel<<<gproj, blk>>>(q, Wq, bq, dQ);
    proj_kernel<<<gproj, blk>>>(k, Wk, bk, dK);
    proj_kernel<<<gproj, blk>>>(v, Wv, bv, dV);

    // 2) scores -> attn region
    dim3 gsc(SEQ/64, SEQ/64, BH);
    scores_kernel<<<gsc, blk>>>(attn);

    // 3) softmax in place
    softmax_kernel<<<BH*SEQ, blk>>>(attn);

    // 4) PV -> merged O
    dim3 gpv(SEQ/64, 1, BH);
    pv_kernel<<<gpv, blk>>>(attn);

    // 5) FC + bias + residual -> X
    dim3 gfc(NROWS/64, DMODEL/64);
    fc_kernel<<<gfc, blk>>>(Wfc, bfc, q);

    // 6) LayerNorm -> y region
    ln_kernel<<<NROWS, blk>>>(gamma, beta, out);
}

// round 17
// speedup vs baseline: 1.4156x; 1.4156x over previous
#include <cuda_runtime.h>
#include <math.h>

#define BATCH 2
#define SEQ   2048
#define DMODEL 512
#define NHEAD 8
#define DK    64
#define NROWS (BATCH*SEQ)        // 4096
#define Y_ELEMS (NROWS*DMODEL)   // 2097152
#define BH (BATCH*NHEAD)         // 16

#define INV_TEMP 0.04419417382415922f
#define LN_EPS 1e-5f

typedef unsigned long long u64;

// Scratch (static device allocs are allowed)
__device__ float g_Q[BH*SEQ*DK];   // [b*H+h][s][dk]
__device__ float g_K[BH*SEQ*DK];
__device__ float g_V[BH*SEQ*DK];
__device__ float g_O[NROWS*DMODEL];
__device__ float g_X[NROWS*DMODEL];

// ---------------------------------------------------------------------------
// Packed fp32x2 FMA helpers (sm_100+ PTX; ptxas never auto-fuses these)
// ---------------------------------------------------------------------------
__device__ __forceinline__ u64 splat2(float x) {
    u64 r; unsigned xi = __float_as_uint(x);
    asm("mov.b64 %0, {%1, %1};" : "=l"(r) : "r"(xi));
    return r;
}
__device__ __forceinline__ void fma2(u64 &acc, u64 a, u64 b) {
    asm("fma.rn.f32x2 %0, %1, %2, %0;" : "+l"(acc) : "l"(a), "l"(b));
}
__device__ __forceinline__ float2 unpack2(u64 v) {
    unsigned lo, hi;
    asm("mov.b64 {%0, %1}, %2;" : "=r"(lo), "=r"(hi) : "l"(v));
    float2 f; f.x = __uint_as_float(lo); f.y = __uint_as_float(hi);
    return f;
}

// 8x8 micro-tile step: a = 8 row values, b = 8 col values (as 4 packed pairs)
__device__ __forceinline__ void micro8x8(const float4& a0, const float4& a1,
                                         const ulonglong2& b0, const ulonglong2& b1,
                                         u64 acc[8][4])
{
    float av[8] = {a0.x,a0.y,a0.z,a0.w,a1.x,a1.y,a1.z,a1.w};
    #pragma unroll
    for (int i = 0; i < 8; i++) {
        u64 s = splat2(av[i]);
        fma2(acc[i][0], s, b0.x);
        fma2(acc[i][1], s, b0.y);
        fma2(acc[i][2], s, b1.x);
        fma2(acc[i][3], s, b1.y);
    }
}

// ---------------------------------------------------------------------------
// Kernel 1: projection  dst[b,h,s,dk] = A[n,:] . W[o,:] + bias[o]
// 128x128 block tile, BK=16, 256 threads, 8x8 micro-tile via FFMA2
// ---------------------------------------------------------------------------
__global__ __launch_bounds__(256, 2) void proj_kernel(
    const float* __restrict__ A, const float* __restrict__ W,
    const float* __restrict__ bias, float* __restrict__ dst)
{
    __shared__ float As[16*128];   // [k][m]
    __shared__ float Ws[16*128];   // [k][n]
    const int t  = threadIdx.x;
    const int tx = t & 15, ty = t >> 4;
    const int row0 = blockIdx.x * 128;
    const int col0 = blockIdx.y * 128;

    u64 acc[8][4];
    #pragma unroll
    for (int i = 0; i < 8; i++)
        #pragma unroll
        for (int j = 0; j < 4; j++) acc[i][j] = 0ull;

    for (int k0 = 0; k0 < DMODEL; k0 += 16) {
        #pragma unroll
        for (int p = 0; p < 2; p++) {
            int f = p*256 + t;
            int r = f & 127, cg = f >> 7;      // cg 0..3
            float4 av = *(const float4*)&A[(size_t)(row0+r)*DMODEL + k0 + cg*4];
            float4 wv = *(const float4*)&W[(size_t)(col0+r)*DMODEL + k0 + cg*4];
            As[(cg*4+0)*128+r]=av.x; As[(cg*4+1)*128+r]=av.y;
            As[(cg*4+2)*128+r]=av.z; As[(cg*4+3)*128+r]=av.w;
            Ws[(cg*4+0)*128+r]=wv.x; Ws[(cg*4+1)*128+r]=wv.y;
            Ws[(cg*4+2)*128+r]=wv.z; Ws[(cg*4+3)*128+r]=wv.w;
        }
        __syncthreads();
        #pragma unroll
        for (int k = 0; k < 16; k++) {
            float4 a0 = *(const float4*)&As[k*128 + ty*4];
            float4 a1 = *(const float4*)&As[k*128 + 64 + ty*4];
            ulonglong2 b0 = *(const ulonglong2*)&Ws[k*128 + tx*4];
            ulonglong2 b1 = *(const ulonglong2*)&Ws[k*128 + 64 + tx*4];
            micro8x8(a0, a1, b0, b1, acc);
        }
        __syncthreads();
    }

    #pragma unroll
    for (int i = 0; i < 8; i++) {
        int n = row0 + ((i < 4) ? ty*4 + i : 64 + ty*4 + (i-4));
        int bb = n >> 11, ss = n & 2047;
        #pragma unroll
        for (int g = 0; g < 2; g++) {
            int o = col0 + g*64 + tx*4;
            int h = o >> 6;
            float2 p0 = unpack2(acc[i][g*2+0]);
            float2 p1 = unpack2(acc[i][g*2+1]);
            float4 v;
            v.x = p0.x + bias[o+0]; v.y = p0.y + bias[o+1];
            v.z = p1.x + bias[o+2]; v.w = p1.y + bias[o+3];
            *(float4*)&dst[(((size_t)(bb*NHEAD+h))*SEQ + ss)*DK + (tx*4)] = v;
        }
    }
}

// ---------------------------------------------------------------------------
// Kernel 2: scores tile 128x128 per (b,h); full dk=64 in smem; FFMA2 8x8
// dynamic smem: Qs[64][128] + Ks[64][128] = 64KB
// ---------------------------------------------------------------------------
__global__ __launch_bounds__(256, 2) void scores_kernel(float* __restrict__ attn)
{
    extern __shared__ float sm[];
    float* Qs = sm;              // [dk][q]
    float* Ks = sm + 64*128;     // [dk][k]
    const int t  = threadIdx.x;
    const int tx = t & 15, ty = t >> 4;
    const int q0 = blockIdx.x * 128;
    const int k0 = blockIdx.y * 128;
    const int bh = blockIdx.z;
    const float* Qb = g_Q + (size_t)bh*SEQ*DK;
    const float* Kb = g_K + (size_t)bh*SEQ*DK;

    #pragma unroll
    for (int p = 0; p < 8; p++) {
        int f = p*256 + t;
        int r = f & 127, cg = f >> 7;          // cg 0..15
        float4 qv = *(const float4*)&Qb[(size_t)(q0 + r)*DK + cg*4];
        float4 kv = *(const float4*)&Kb[(size_t)(k0 + r)*DK + cg*4];
        Qs[(cg*4+0)*128+r]=qv.x; Qs[(cg*4+1)*128+r]=qv.y;
        Qs[(cg*4+2)*128+r]=qv.z; Qs[(cg*4+3)*128+r]=qv.w;
        Ks[(cg*4+0)*128+r]=kv.x; Ks[(cg*4+1)*128+r]=kv.y;
        Ks[(cg*4+2)*128+r]=kv.z; Ks[(cg*4+3)*128+r]=kv.w;
    }
    __syncthreads();

    u64 acc[8][4];
    #pragma unroll
    for (int i = 0; i < 8; i++)
        #pragma unroll
        for (int j = 0; j < 4; j++) acc[i][j] = 0ull;

    #pragma unroll 8
    for (int k = 0; k < 64; k++) {
        float4 a0 = *(const float4*)&Qs[k*128 + ty*4];
        float4 a1 = *(const float4*)&Qs[k*128 + 64 + ty*4];
        ulonglong2 b0 = *(const ulonglong2*)&Ks[k*128 + tx*4];
        ulonglong2 b1 = *(const ulonglong2*)&Ks[k*128 + 64 + tx*4];
        micro8x8(a0, a1, b0, b1, acc);
    }

    const int b = bh >> 3, h = bh & 7;
    float* obase = attn + ((size_t)(h*BATCH + b))*SEQ*SEQ;
    #pragma unroll
    for (int i = 0; i < 8; i++) {
        int r = (i < 4) ? ty*4 + i : 64 + ty*4 + (i-4);
        size_t rowoff = (size_t)(q0 + r) * SEQ;
        #pragma unroll
        for (int g = 0; g < 2; g++) {
            float2 p0 = unpack2(acc[i][g*2+0]);
            float2 p1 = unpack2(acc[i][g*2+1]);
            float4 v;
            v.x = p0.x * INV_TEMP; v.y = p0.y * INV_TEMP;
            v.z = p1.x * INV_TEMP; v.w = p1.y * INV_TEMP;
            *(float4*)&obase[rowoff + k0 + g*64 + tx*4] = v;
        }
    }
}

// ---------------------------------------------------------------------------
// Kernel 3: row softmax in place over rows of length 2048 (unchanged)
// ---------------------------------------------------------------------------
__global__ __launch_bounds__(256) void softmax_kernel(float* __restrict__ attn)
{
    __shared__ float sbuf[8];
    float* p = attn + (size_t)blockIdx.x * SEQ;
    const int t = threadIdx.x;

    float4 v0 = ((const float4*)p)[t];
    float4 v1 = ((const float4*)p)[t + 256];

    float m = fmaxf(fmaxf(fmaxf(v0.x, v0.y), fmaxf(v0.z, v0.w)),
                    fmaxf(fmaxf(v1.x, v1.y), fmaxf(v1.z, v1.w)));
    #pragma unroll
    for (int o = 16; o > 0; o >>= 1) m = fmaxf(m, __shfl_xor_sync(0xffffffffu, m, o));
    if ((t & 31) == 0) sbuf[t >> 5] = m;
    __syncthreads();
    m = sbuf[0];
    #pragma unroll
    for (int w = 1; w < 8; w++) m = fmaxf(m, sbuf[w]);
    __syncthreads();

    v0.x = __expf(v0.x - m); v0.y = __expf(v0.y - m);
    v0.z = __expf(v0.z - m); v0.w = __expf(v0.w - m);
    v1.x = __expf(v1.x - m); v1.y = __expf(v1.y - m);
    v1.z = __expf(v1.z - m); v1.w = __expf(v1.w - m);

    float s = v0.x + v0.y + v0.z + v0.w + v1.x + v1.y + v1.z + v1.w;
    #pragma unroll
    for (int o = 16; o > 0; o >>= 1) s += __shfl_xor_sync(0xffffffffu, s, o);
    if ((t & 31) == 0) sbuf[t >> 5] = s;
    __syncthreads();
    s = sbuf[0];
    #pragma unroll
    for (int w = 1; w < 8; w++) s += sbuf[w];

    float inv = 1.0f / s;
    v0.x *= inv; v0.y *= inv; v0.z *= inv; v0.w *= inv;
    v1.x *= inv; v1.y *= inv; v1.z *= inv; v1.w *= inv;
    ((float4*)p)[t] = v0;
    ((float4*)p)[t + 256] = v1;
}

// ---------------------------------------------------------------------------
// Kernel 4: O[b, q, h*64+dk] = attn[h*B+b, q, :] . Vh
// 128q x 64dk tile, BK=32, 128 threads, 8x8 micro-tile via FFMA2
// As kept [q][k] with pad-37 row stride (conflict-free scalar a-reads)
// ---------------------------------------------------------------------------
#define PV_LDA 37
__global__ __launch_bounds__(128, 4) void pv_kernel(const float* __restrict__ attn)
{
    __shared__ float As[128*PV_LDA];   // [q][k] padded
    __shared__ float Bs[32*64];        // [k][dk]
    const int t  = threadIdx.x;
    const int tx = t & 7, ty = t >> 3;     // ty 0..15
    const int q0 = blockIdx.x * 128;
    const int bh = blockIdx.z;
    const int b = bh >> 3, h = bh & 7;
    const float* Ab = attn + ((size_t)(h*BATCH + b))*SEQ*SEQ;
    const float* Vb = g_V + (size_t)bh*SEQ*DK;

    u64 acc[8][4];
    #pragma unroll
    for (int i = 0; i < 8; i++)
        #pragma unroll
        for (int j = 0; j < 4; j++) acc[i][j] = 0ull;

    for (int kk = 0; kk < SEQ; kk += 32) {
        #pragma unroll
        for (int p = 0; p < 8; p++) {
            int f = p*128 + t;
            int r = f >> 3, c = f & 7;
            float4 av = *(const float4*)&Ab[(size_t)(q0+r)*SEQ + kk + c*4];
            As[r*PV_LDA + c*4 + 0] = av.x;
            As[r*PV_LDA + c*4 + 1] = av.y;
            As[r*PV_LDA + c*4 + 2] = av.z;
            As[r*PV_LDA + c*4 + 3] = av.w;
        }
        #pragma unroll
        for (int p = 0; p < 4; p++) {
            int f = p*128 + t;
            int r = f >> 4, c = f & 15;
            *(float4*)&Bs[r*64 + c*4] = *(const float4*)&Vb[(size_t)(kk+r)*DK + c*4];
        }
        __syncthreads();
        #pragma unroll 8
        for (int k = 0; k < 32; k++) {
            ulonglong2 b0 = *(const ulonglong2*)&Bs[k*64 + tx*4];
            ulonglong2 b1 = *(const ulonglong2*)&Bs[k*64 + 32 + tx*4];
            float4 a0, a1;
            a0.x = As[(ty*4+0)*PV_LDA + k];
            a0.y = As[(ty*4+1)*PV_LDA + k];
            a0.z = As[(ty*4+2)*PV_LDA + k];
            a0.w = As[(ty*4+3)*PV_LDA + k];
            a1.x = As[(64+ty*4+0)*PV_LDA + k];
            a1.y = As[(64+ty*4+1)*PV_LDA + k];
            a1.z = As[(64+ty*4+2)*PV_LDA + k];
            a1.w = As[(64+ty*4+3)*PV_LDA + k];
            micro8x8(a0, a1, b0, b1, acc);
        }
        __syncthreads();
    }

    #pragma unroll
    for (int i = 0; i < 8; i++) {
        int r = (i < 4) ? ty*4 + i : 64 + ty*4 + (i-4);
        size_t n = (size_t)(b*SEQ + q0 + r);
        #pragma unroll
        for (int g = 0; g < 2; g++) {
            float2 p0 = unpack2(acc[i][g*2+0]);
            float2 p1 = unpack2(acc[i][g*2+1]);
            float4 v; v.x = p0.x; v.y = p0.y; v.z = p1.x; v.w = p1.y;
            *(float4*)&g_O[n*DMODEL + h*DK + g*32 + tx*4] = v;
        }
    }
}

// ---------------------------------------------------------------------------
// Kernel 5: X[n,o] = O[n,:] . Wfc[o,:] + bfc[o] + resid[n,o]  (FFMA2 128x128)
// ---------------------------------------------------------------------------
__global__ __launch_bounds__(256, 2) void fc_kernel(
    const float* __restrict__ W, const float* __restrict__ bias,
    const float* __restrict__ resid)
{
    __shared__ float As[16*128];
    __shared__ float Ws[16*128];
    const int t  = threadIdx.x;
    const int tx = t & 15, ty = t >> 4;
    const int row0 = blockIdx.x * 128;
    const int col0 = blockIdx.y * 128;

    u64 acc[8][4];
    #pragma unroll
    for (int i = 0; i < 8; i++)
        #pragma unroll
        for (int j = 0; j < 4; j++) acc[i][j] = 0ull;

    for (int k0 = 0; k0 < DMODEL; k0 += 16) {
        #pragma unroll
        for (int p = 0; p < 2; p++) {
            int f = p*256 + t;
            int r = f & 127, cg = f >> 7;
            float4 av = *(const float4*)&g_O[(size_t)(row0+r)*DMODEL + k0 + cg*4];
            float4 wv = *(const float4*)&W[(size_t)(col0+r)*DMODEL + k0 + cg*4];
            As[(cg*4+0)*128+r]=av.x; As[(cg*4+1)*128+r]=av.y;
            As[(cg*4+2)*128+r]=av.z; As[(cg*4+3)*128+r]=av.w;
            Ws[(cg*4+0)*128+r]=wv.x; Ws[(cg*4+1)*128+r]=wv.y;
            Ws[(cg*4+2)*128+r]=wv.z; Ws[(cg*4+3)*128+r]=wv.w;
        }
        __syncthreads();
        #pragma unroll
        for (int k = 0; k < 16; k++) {
            float4 a0 = *(const float4*)&As[k*128 + ty*4];
            float4 a1 = *(const float4*)&As[k*128 + 64 + ty*4];
            ulonglong2 b0 = *(const ulonglong2*)&Ws[k*128 + tx*4];
            ulonglong2 b1 = *(const ulonglong2*)&Ws[k*128 + 64 + tx*4];
            micro8x8(a0, a1, b0, b1, acc);
        }
        __syncthreads();
    }

    #pragma unroll
    for (int i = 0; i < 8; i++) {
        size_t n = (size_t)(row0 + ((i < 4) ? ty*4 + i : 64 + ty*4 + (i-4)));
        #pragma unroll
        for (int g = 0; g < 2; g++) {
            int o = col0 + g*64 + tx*4;
            float2 p0 = unpack2(acc[i][g*2+0]);
            float2 p1 = unpack2(acc[i][g*2+1]);
            float4 rv = *(const float4*)&resid[n*DMODEL + o];
            float4 v;
            v.x = p0.x + bias[o+0] + rv.x;
            v.y = p0.y + bias[o+1] + rv.y;
            v.z = p1.x + bias[o+2] + rv.z;
            v.w = p1.y + bias[o+3] + rv.w;
            *(float4*)&g_X[n*DMODEL + o] = v;
        }
    }
}

// ---------------------------------------------------------------------------
// Kernel 6: LayerNorm over rows of 512 -> y region of d_out (unchanged)
// ---------------------------------------------------------------------------
__global__ __launch_bounds__(256) void ln_kernel(
    const float* __restrict__ gamma, const float* __restrict__ beta,
    float* __restrict__ Y)
{
    __shared__ float sbuf[16];
    const size_t row = blockIdx.x;
    const int t = threadIdx.x;
    const float* x = g_X + row*DMODEL;

    float2 v = ((const float2*)x)[t];
    float s  = v.x + v.y;
    float ss = v.x*v.x + v.y*v.y;
    #pragma unroll
    for (int o = 16; o > 0; o >>= 1) {
        s  += __shfl_xor_sync(0xffffffffu, s, o);
        ss += __shfl_xor_sync(0xffffffffu, ss, o);
    }
    if ((t & 31) == 0) { sbuf[t >> 5] = s; sbuf[8 + (t >> 5)] = ss; }
    __syncthreads();
    s = 0.f; ss = 0.f;
    #pragma unroll
    for (int w = 0; w < 8; w++) { s += sbuf[w]; ss += sbuf[8 + w]; }

    float mu  = s * (1.0f / DMODEL);
    float var = ss * (1.0f / DMODEL) - mu * mu;
    float inv = rsqrtf(var + LN_EPS);

    float2 g = ((const float2*)gamma)[t];
    float2 bt = ((const float2*)beta)[t];
    float2 y;
    y.x = (v.x - mu) * inv * g.x + bt.x;
    y.y = (v.y - mu) * inv * g.y + bt.y;
    ((float2*)(Y + row*DMODEL))[t] = y;
}

// ---------------------------------------------------------------------------
extern "C" void kernel_launch(void* const* d_in, const int* in_sizes, int n_in,
                              void* d_out, int out_size)
{
    (void)in_sizes; (void)n_in; (void)out_size;
    const float* q     = (const float*)d_in[0];
    const float* k     = (const float*)d_in[1];
    const float* v     = (const float*)d_in[2];
    const float* Wq    = (const float*)d_in[3];
    const float* bq    = (const float*)d_in[4];
    const float* Wk    = (const float*)d_in[5];
    const float* bk    = (const float*)d_in[6];
    const float* Wv    = (const float*)d_in[7];
    const float* bv    = (const float*)d_in[8];
    const float* Wfc   = (const float*)d_in[9];
    const float* bfc   = (const float*)d_in[10];
    const float* gamma = (const float*)d_in[11];
    const float* beta  = (const float*)d_in[12];

    float* out  = (float*)d_out;
    float* attn = out + Y_ELEMS;

    float* dQ; cudaGetSymbolAddress((void**)&dQ, g_Q);
    float* dK; cudaGetSymbolAddress((void**)&dK, g_K);
    float* dV; cudaGetSymbolAddress((void**)&dV, g_V);

    // scores kernel needs 64KB dynamic smem (opt-in)
    static_assert(64*128*2*sizeof(float) == 65536, "smem");
    cudaFuncSetAttribute(scores_kernel,
                         cudaFuncAttributeMaxDynamicSharedMemorySize, 65536);

    // 1) QKV projections into head-split layout
    dim3 gproj(NROWS/128, DMODEL/128);
    proj_kernel<<<gproj, 256>>>(q, Wq, bq, dQ);
    proj_kernel<<<gproj, 256>>>(k, Wk, bk, dK);
    proj_kernel<<<gproj, 256>>>(v, Wv, bv, dV);

    // 2) scores -> attn region (scaled by 1/sqrt(d_model))
    dim3 gsc(SEQ/128, SEQ/128, BH);
    scores_kernel<<<gsc, 256, 65536>>>(attn);

    // 3) softmax in place
    softmax_kernel<<<BH*SEQ, 256>>>(attn);

    // 4) PV -> merged O
    dim3 gpv(SEQ/128, 1, BH);
    pv_kernel<<<gpv, 128>>>(attn);

    // 5) FC + bias + residual -> X
    dim3 gfc(NROWS/128, DMODEL/128);
    fc_kernel<<<gfc, 256>>>(Wfc, bfc, q);

    // 6) LayerNorm -> y region
    ln_kernel<<<NROWS, 256>>>(gamma, beta, out);
}